// round 1
// baseline (speedup 1.0000x reference)
#include <cuda_runtime.h>
#include <cstdint>

// 2D snake-scan RNN log-prob evaluation.
// One warp per sample. Lane j owns column j of WcH/WcV (in regs, f32x2-packed).
// h kept replicated per lane; redistributed each step through shared memory.

#define FULLMASK 0xFFFFFFFFu

static constexpr int L = 64;
static constexpr int H = 32;
static constexpr int WARPS_PER_CTA = 4;
static constexpr int B = 1024;

__device__ __forceinline__ unsigned long long pack2(float lo, float hi) {
    unsigned long long r;
    asm("mov.b64 %0, {%1, %2};" : "=l"(r) : "f"(lo), "f"(hi));
    return r;
}
__device__ __forceinline__ void unpack2(unsigned long long v, float& lo, float& hi) {
    asm("mov.b64 {%0, %1}, %2;" : "=f"(lo), "=f"(hi) : "l"(v));
}
__device__ __forceinline__ unsigned long long ffma2(unsigned long long a,
                                                    unsigned long long b,
                                                    unsigned long long c) {
    unsigned long long d;
    asm("fma.rn.f32x2 %0, %1, %2, %3;" : "=l"(d) : "l"(a), "l"(b), "l"(c));
    return d;
}
__device__ __forceinline__ unsigned long long fadd2(unsigned long long a,
                                                    unsigned long long b) {
    unsigned long long d;
    asm("add.rn.f32x2 %0, %1, %2;" : "=l"(d) : "l"(a), "l"(b));
    return d;
}

__global__ void __launch_bounds__(WARPS_PER_CTA * 32, 1)
rnn2d_kernel(const int* __restrict__ x,        // [B, L, L] int32 in {0,1}
             const float* __restrict__ Win,    // [4, H]
             const float* __restrict__ WcH,    // [H, H]
             const float* __restrict__ WcV,    // [H, H]
             const float* __restrict__ bV,     // [H]
             const float* __restrict__ Wout,   // [H, 2]
             const float* __restrict__ bout,   // [2]
             float* __restrict__ out)          // [B]
{
    __shared__ __align__(16) float rowcarry[WARPS_PER_CTA][L * H]; // 8KB per warp
    __shared__ int xbuf[WARPS_PER_CTA][2][L];

    const int lane = threadIdx.x & 31;
    const int w = threadIdx.x >> 5;
    const int sample = blockIdx.x * WARPS_PER_CTA + w;

    float* rc = rowcarry[w];

    // Zero-init rowcarry (row 0 sees cV = 0).
    {
        float4* rc4 = reinterpret_cast<float4*>(rc);
        #pragma unroll
        for (int k = 0; k < (L * H) / (4 * 32); k++)
            rc4[k * 32 + lane] = make_float4(0.f, 0.f, 0.f, 0.f);
    }
    // Row 0's "previous row" buffer: sentinel -1 (no vertical input).
    xbuf[w][1][lane] = -1;
    xbuf[w][1][lane + 32] = -1;

    // ---- Per-lane weights ----
    const float win0 = Win[0 * H + lane];
    const float win1 = Win[1 * H + lane];
    const float win2 = Win[2 * H + lane];
    const float win3 = Win[3 * H + lane];
    const float bv   = bV[lane];
    const float dwo  = Wout[lane * 2 + 0] - Wout[lane * 2 + 1]; // out0 - out1 direction
    const float dbo  = bout[0] - bout[1];

    unsigned long long wch[16], wcv[16];
    #pragma unroll
    for (int k = 0; k < 16; k++) {
        wch[k] = pack2(WcH[(2 * k) * H + lane], WcH[(2 * k + 1) * H + lane]);
        wcv[k] = pack2(WcV[(2 * k) * H + lane], WcV[(2 * k + 1) * H + lane]);
    }

    const int* xs = x + (long)sample * (L * L);

    unsigned long long hrep[16];   // replicated h (all 32 values, f32x2 pairs)
    unsigned long long cvrep[16];  // replicated vertical carry for current column
    float logacc = 0.f;

    __syncwarp();   // rowcarry init visible to all lanes of this warp

    for (int r = 0; r < L; r++) {
        const int cur = r & 1, prv = cur ^ 1;
        // Load this row of x into shared (lane-coalesced global reads).
        xbuf[w][cur][lane]      = xs[r * L + lane];
        xbuf[w][cur][lane + 32] = xs[r * L + lane + 32];
        __syncwarp();

        const int dir = (r & 1) ? -1 : 1;
        int c = (r & 1) ? (L - 1) : 0;

        // hcarry resets to zero at each row start.
        #pragma unroll
        for (int k = 0; k < 16; k++) hrep[k] = 0ull;

        // Vertical carry for the first column of this row (prev row's h there;
        // zeros for r == 0 since rowcarry was zero-initialized).
        {
            const ulonglong2* cp = reinterpret_cast<const ulonglong2*>(rc + (c << 5));
            #pragma unroll
            for (int k = 0; k < 8; k++) {
                ulonglong2 v = cp[k];
                cvrep[2 * k] = v.x; cvrep[2 * k + 1] = v.y;
            }
        }

        int a = -1;  // no left-neighbor (scan order) at row start

        #pragma unroll 2
        for (int j = 0; j < L; j++) {
            const int xc = xbuf[w][cur][c];
            const int bb = xbuf[w][prv][c];

            // One-hot input contribution: Win[a] + Win[2+b] + bV (zero rows if absent)
            const float wa = (a == 0) ? win0 : ((a == 1) ? win1 : 0.f);
            const float wb = (bb == 0) ? win2 : ((bb == 1) ? win3 : 0.f);
            const float rsum = bv + wa + wb;

            // pre[lane] = sum_i h[i]*WcH[i,lane] + sum_i cV[i]*WcV[i,lane]
            unsigned long long a0 = 0ull, a1 = 0ull, a2 = 0ull, a3 = 0ull;
            #pragma unroll
            for (int k = 0; k < 16; k += 4) {
                a0 = ffma2(hrep[k + 0], wch[k + 0], a0);
                a1 = ffma2(hrep[k + 1], wch[k + 1], a1);
                a2 = ffma2(hrep[k + 2], wch[k + 2], a2);
                a3 = ffma2(hrep[k + 3], wch[k + 3], a3);
            }
            #pragma unroll
            for (int k = 0; k < 16; k += 4) {
                a0 = ffma2(cvrep[k + 0], wcv[k + 0], a0);
                a1 = ffma2(cvrep[k + 1], wcv[k + 1], a1);
                a2 = ffma2(cvrep[k + 2], wcv[k + 2], a2);
                a3 = ffma2(cvrep[k + 3], wcv[k + 3], a3);
            }
            a0 = fadd2(a0, a1);
            a2 = fadd2(a2, a3);
            a0 = fadd2(a0, a2);
            float slo, shi;
            unpack2(a0, slo, shi);
            const float pre = slo + shi + rsum;

            // ELU (alpha = 1)
            const float hnew = (pre > 0.f) ? pre : (__expf(pre) - 1.f);

            // Store: serves (a) h redistribution for next column,
            //        (b) vertical carry for the row below at this column.
            rc[(c << 5) + lane] = hnew;
            __syncwarp();

            const int cn = (j == L - 1) ? c : (c + dir);

            // Reload replicated h (next column's hcarry) ...
            {
                const ulonglong2* hp = reinterpret_cast<const ulonglong2*>(rc + (c << 5));
                #pragma unroll
                for (int k = 0; k < 8; k++) {
                    ulonglong2 v = hp[k];
                    hrep[2 * k] = v.x; hrep[2 * k + 1] = v.y;
                }
            }
            // ... and the vertical carry for the next column (still prev-row value;
            // at j == L-1 this correctly picks up the just-written value, which is
            // exactly the next row's first vertical carry).
            {
                const ulonglong2* cp = reinterpret_cast<const ulonglong2*>(rc + (cn << 5));
                #pragma unroll
                for (int k = 0; k < 8; k++) {
                    ulonglong2 v = cp[k];
                    cvrep[2 * k] = v.x; cvrep[2 * k + 1] = v.y;
                }
            }

            // Output head (d = 2): q = h.(Wout0 - Wout1) + (bout0 - bout1)
            // logp = -softplus(q)  if x == 1,  -softplus(-q) if x == 0
            float q = hnew * dwo;
            #pragma unroll
            for (int off = 16; off; off >>= 1)
                q += __shfl_xor_sync(FULLMASK, q, off);
            q += dbo;
            const float t = (xc == 1) ? q : -q;
            const float sp = fmaxf(t, 0.f) + __logf(1.f + __expf(-fabsf(t)));
            logacc -= sp;

            a = xc;
            c = cn;
        }
    }

    if (lane == 0) out[sample] = 0.5f * logacc;
}

extern "C" void kernel_launch(void* const* d_in, const int* in_sizes, int n_in,
                              void* d_out, int out_size)
{
    const int*   x    = (const int*)  d_in[0];
    const float* Win  = (const float*)d_in[1];
    const float* WcH  = (const float*)d_in[2];
    const float* WcV  = (const float*)d_in[3];
    const float* bV   = (const float*)d_in[4];
    const float* Wout = (const float*)d_in[5];
    const float* bout = (const float*)d_in[6];
    float* out = (float*)d_out;

    dim3 grid(B / WARPS_PER_CTA);           // 256 CTAs
    dim3 block(WARPS_PER_CTA * 32);         // 128 threads = 4 samples
    rnn2d_kernel<<<grid, block>>>(x, Win, WcH, WcV, bV, Wout, bout, out);
}